// round 1
// baseline (speedup 1.0000x reference)
#include <cuda_runtime.h>
#include <cstdint>

// Shapes (fixed by the problem)
#define B_ 2
#define S_ 1024
#define H_ 512
#define A_ 128

// ---------------- scratch (no allocation allowed) ----------------
__device__ float g_wxux[B_ * S_ * 2 * A_];   // [m=b*S+s][0:128]=wx, [128:256]=ux  (2 MB)
__device__ float g_colsum[B_ * S_];          // sum over i of attn[b,i,j]

__device__ __forceinline__ float tanh_fast(float x) {
    float y;
    asm("tanh.approx.f32 %0, %1;" : "=f"(y) : "f"(x));
    return y;
}

// ---------------- kernel 0: zero colsum + context region ----------------
__global__ void zero_kernel(float* ctx) {
    int t = blockIdx.x * blockDim.x + threadIdx.x;
    if (t < B_ * S_) g_colsum[t] = 0.0f;
    if (t < B_ * H_) ctx[t] = 0.0f;
}

// ---------------- kernel 1: [wx|ux] = lstm(2048x512) @ [w|u](512x256) ----------------
#define BM 64
#define BN 64
#define BK 16
__global__ __launch_bounds__(256) void gemm_wxux(
    const float* __restrict__ lstm, const float* __restrict__ w, const float* __restrict__ u)
{
    __shared__ float As[BK][BM];
    __shared__ float Bs[BK][BN];
    int tid = threadIdx.x;
    int m0 = blockIdx.x * BM;                  // 32 blocks
    int n0 = blockIdx.y * BN;                  // 4 blocks (0,64 -> w; 128,192 -> u)
    const float* bsrc = (n0 < A_) ? (w + n0) : (u + (n0 - A_));

    int tm = (tid >> 4) * 4;                   // 0..60
    int tn = (tid & 15) * 4;                   // 0..60
    int la_m = tid >> 2;                       // 0..63
    int la_k = (tid & 3) * 4;                  // 0,4,8,12
    int lb_k = tid >> 4;                       // 0..15
    int lb_n = (tid & 15) * 4;                 // 0..60

    float acc[4][4];
#pragma unroll
    for (int i = 0; i < 4; i++)
#pragma unroll
        for (int j = 0; j < 4; j++) acc[i][j] = 0.0f;

    for (int k0 = 0; k0 < H_; k0 += BK) {
        float4 av = *(const float4*)(lstm + (size_t)(m0 + la_m) * H_ + k0 + la_k);
        float4 bv = *(const float4*)(bsrc + (size_t)(k0 + lb_k) * A_ + lb_n);
        __syncthreads();
        As[la_k + 0][la_m] = av.x;
        As[la_k + 1][la_m] = av.y;
        As[la_k + 2][la_m] = av.z;
        As[la_k + 3][la_m] = av.w;
        *(float4*)&Bs[lb_k][lb_n] = bv;
        __syncthreads();
#pragma unroll
        for (int kk = 0; kk < BK; kk++) {
            float4 a4 = *(const float4*)&As[kk][tm];
            float4 b4 = *(const float4*)&Bs[kk][tn];
            float am[4] = {a4.x, a4.y, a4.z, a4.w};
            float bn[4] = {b4.x, b4.y, b4.z, b4.w};
#pragma unroll
            for (int i = 0; i < 4; i++)
#pragma unroll
                for (int j = 0; j < 4; j++) acc[i][j] = fmaf(am[i], bn[j], acc[i][j]);
        }
    }
#pragma unroll
    for (int i = 0; i < 4; i++) {
        float4 o = make_float4(acc[i][0], acc[i][1], acc[i][2], acc[i][3]);
        *(float4*)(g_wxux + (size_t)(m0 + tm + i) * (2 * A_) + n0 + tn) = o;
    }
}

// ---------------- kernel 2: e = tanh-sum, softmax, attn write, colsum ----------------
#define TI 16
#define TJ 64
// dynamic smem: e_buf[TI][1024] + wx_s[TI][128] + ux_s[TJ][128] + v_s[128]
__global__ __launch_bounds__(256) void attn_e_kernel(
    const float* __restrict__ v, float* __restrict__ attn_out)
{
    extern __shared__ float sm[];
    float* e_buf = sm;                         // TI*1024
    float* wx_s  = e_buf + TI * S_;            // TI*128
    float* ux_s  = wx_s + TI * A_;             // TJ*128
    float* v_s   = ux_s + TJ * A_;             // 128

    int tid = threadIdx.x;
    int blk = blockIdx.x;                      // 128 blocks: b*(S/TI)+it
    int b   = blk >> 6;                        // /(S_/TI = 64)
    int i0  = (blk & 63) * TI;

    const float* wxbase = g_wxux + (size_t)(b * S_ + i0) * (2 * A_);
    // load wx rows (TI x 128)
    for (int x = tid; x < TI * A_ / 4; x += 256) {
        int r = x >> 5, c = x & 31;
        ((float4*)wx_s)[x] = *(const float4*)(wxbase + (size_t)r * (2 * A_) + c * 4);
    }
    if (tid < 32) ((float4*)v_s)[tid] = ((const float4*)v)[tid];

    int i2 = tid >> 5;                         // rows 2*i2, 2*i2+1  (0..7)
    int j2 = tid & 31;                         // cols 2*j2, 2*j2+1  (0..31 of TJ)

    for (int jt = 0; jt < S_; jt += TJ) {
        __syncthreads();                       // protect ux_s reuse
        const float* uxbase = g_wxux + (size_t)(b * S_ + jt) * (2 * A_) + A_;
        for (int x = tid; x < TJ * A_ / 4; x += 256) {
            int r = x >> 5, c = x & 31;
            ((float4*)ux_s)[x] = *(const float4*)(uxbase + (size_t)r * (2 * A_) + c * 4);
        }
        __syncthreads();

        float acc00 = 0.f, acc01 = 0.f, acc10 = 0.f, acc11 = 0.f;
        const float* wr0 = wx_s + (2 * i2) * A_;
        const float* wr1 = wr0 + A_;
        const float* ur0 = ux_s + (2 * j2) * A_;
        const float* ur1 = ur0 + A_;
#pragma unroll 4
        for (int a = 0; a < A_; a += 4) {
            float4 w0 = *(const float4*)(wr0 + a);
            float4 w1 = *(const float4*)(wr1 + a);
            float4 u0 = *(const float4*)(ur0 + a);
            float4 u1 = *(const float4*)(ur1 + a);
            float4 vv = *(const float4*)(v_s + a);
#define DO(c) { float vc = vv.c; \
            acc00 = fmaf(tanh_fast(w0.c + u0.c), vc, acc00); \
            acc01 = fmaf(tanh_fast(w0.c + u1.c), vc, acc01); \
            acc10 = fmaf(tanh_fast(w1.c + u0.c), vc, acc10); \
            acc11 = fmaf(tanh_fast(w1.c + u1.c), vc, acc11); }
            DO(x) DO(y) DO(z) DO(w)
#undef DO
        }
        int jb = jt + 2 * j2;
        e_buf[(2 * i2 + 0) * S_ + jb + 0] = acc00;
        e_buf[(2 * i2 + 0) * S_ + jb + 1] = acc01;
        e_buf[(2 * i2 + 1) * S_ + jb + 0] = acc10;
        e_buf[(2 * i2 + 1) * S_ + jb + 1] = acc11;
    }
    __syncthreads();

    // softmax per row (warp per row, 8 warps x 2 passes covers 16 rows)
    int warp = tid >> 5, lane = tid & 31;
    for (int r = warp; r < TI; r += 8) {
        float* row = e_buf + (size_t)r * S_;
        float m = -1e30f;
        for (int j = lane; j < S_; j += 32) m = fmaxf(m, row[j]);
#pragma unroll
        for (int o = 16; o; o >>= 1) m = fmaxf(m, __shfl_xor_sync(0xffffffffu, m, o));
        float s = 0.f;
        for (int j = lane; j < S_; j += 32) {
            float p = __expf(row[j] - m);
            row[j] = p;
            s += p;
        }
#pragma unroll
        for (int o = 16; o; o >>= 1) s += __shfl_xor_sync(0xffffffffu, s, o);
        float inv = 1.0f / s;
        float* orow = attn_out + (size_t)(b * S_ + i0 + r) * S_;
        for (int j = lane; j < S_; j += 32) {
            float p = row[j] * inv;
            row[j] = p;
            orow[j] = p;
        }
    }
    __syncthreads();

    // column sums over this block's TI rows -> global colsum
    for (int j = tid; j < S_; j += 256) {
        float s = 0.f;
#pragma unroll
        for (int r = 0; r < TI; r++) s += e_buf[(size_t)r * S_ + j];
        atomicAdd(&g_colsum[b * S_ + j], s);
    }
}

// ---------------- kernel 3: context[b,h] = sum_j colsum[b,j] * lstm[b,j,h] ----------------
__global__ __launch_bounds__(512) void context_kernel(
    const float* __restrict__ lstm, float* __restrict__ ctx)
{
    int b  = blockIdx.x >> 4;                  // 2 * 16 blocks
    int j0 = (blockIdx.x & 15) * 64;
    int h  = threadIdx.x;                      // 512 threads = H
    __shared__ float cs[64];
    if (threadIdx.x < 64) cs[threadIdx.x] = g_colsum[b * S_ + j0 + threadIdx.x];
    __syncthreads();
    float acc = 0.f;
    const float* lp = lstm + ((size_t)(b * S_ + j0)) * H_ + h;
#pragma unroll 8
    for (int j = 0; j < 64; j++) acc = fmaf(cs[j], lp[(size_t)j * H_], acc);
    atomicAdd(&ctx[b * H_ + h], acc);
}

// ---------------- launch ----------------
extern "C" void kernel_launch(void* const* d_in, const int* in_sizes, int n_in,
                              void* d_out, int out_size)
{
    const float* lstm = (const float*)d_in[0];
    const float* w    = (const float*)d_in[1];
    const float* u    = (const float*)d_in[2];
    const float* v    = (const float*)d_in[3];
    float* out  = (float*)d_out;
    float* ctx  = out;                // (B,H) = 1024 floats first
    float* attn = out + B_ * H_;      // (B,S,S) = 2M floats after

    zero_kernel<<<8, 256>>>(ctx);
    gemm_wxux<<<dim3(32, 4), 256>>>(lstm, w, u);

    size_t smem = (size_t)(TI * S_ + TI * A_ + TJ * A_ + A_) * sizeof(float); // ~104.5 KB
    cudaFuncSetAttribute(attn_e_kernel, cudaFuncAttributeMaxDynamicSharedMemorySize, (int)smem);
    attn_e_kernel<<<B_ * (S_ / TI), 256, smem>>>(v, attn);

    context_kernel<<<B_ * 16, 512>>>(lstm, ctx);
}

// round 2
// speedup vs baseline: 1.7629x; 1.7629x over previous
#include <cuda_runtime.h>
#include <cstdint>

// Shapes (fixed by the problem)
#define B_ 2
#define S_ 1024
#define H_ 512
#define A_ 128

// ---------------- scratch (no allocation allowed) ----------------
__device__ float g_wx [B_ * S_ * A_];        // [m=b*S+s][a]  row-major (1 MB)
__device__ float g_uxt[B_ * A_ * S_];        // [b][a][s]     a-major / transposed (1 MB)
__device__ float g_colsum[B_ * S_];          // sum over i of attn[b,i,j]

__device__ __forceinline__ float tanh_fast(float x) {
    float y;
    asm("tanh.approx.f32 %0, %1;" : "=f"(y) : "f"(x));
    return y;
}

// ---------------- kernel 0: zero colsum + context region ----------------
__global__ void zero_kernel(float* ctx) {
    int t = blockIdx.x * blockDim.x + threadIdx.x;
    if (t < B_ * S_) g_colsum[t] = 0.0f;
    if (t < B_ * H_) ctx[t] = 0.0f;
}

// ---------------- kernel 1: wx = lstm@w (row-major), uxt = (lstm@u)^T ----------------
#define BM 64
#define BN 64
#define BK 16
__global__ __launch_bounds__(256) void gemm_wxux(
    const float* __restrict__ lstm, const float* __restrict__ w, const float* __restrict__ u)
{
    __shared__ float As[BK][BM];
    __shared__ float Bs[BK][BN];
    int tid = threadIdx.x;
    int m0 = blockIdx.x * BM;                  // 32 blocks (m = b*S+s)
    int n0 = blockIdx.y * BN;                  // 4 blocks: 0,64 -> w ; 128,192 -> u
    const float* bsrc = (n0 < A_) ? (w + n0) : (u + (n0 - A_));

    int tm = (tid >> 4) * 4;                   // 0..60
    int tn = (tid & 15) * 4;                   // 0..60
    int la_m = tid >> 2;                       // 0..63
    int la_k = (tid & 3) * 4;                  // 0,4,8,12
    int lb_k = tid >> 4;                       // 0..15
    int lb_n = (tid & 15) * 4;                 // 0..60

    float acc[4][4];
#pragma unroll
    for (int i = 0; i < 4; i++)
#pragma unroll
        for (int j = 0; j < 4; j++) acc[i][j] = 0.0f;

    for (int k0 = 0; k0 < H_; k0 += BK) {
        float4 av = *(const float4*)(lstm + (size_t)(m0 + la_m) * H_ + k0 + la_k);
        float4 bv = *(const float4*)(bsrc + (size_t)(k0 + lb_k) * A_ + lb_n);
        __syncthreads();
        As[la_k + 0][la_m] = av.x;
        As[la_k + 1][la_m] = av.y;
        As[la_k + 2][la_m] = av.z;
        As[la_k + 3][la_m] = av.w;
        *(float4*)&Bs[lb_k][lb_n] = bv;
        __syncthreads();
#pragma unroll
        for (int kk = 0; kk < BK; kk++) {
            float4 a4 = *(const float4*)&As[kk][tm];
            float4 b4 = *(const float4*)&Bs[kk][tn];
            float am[4] = {a4.x, a4.y, a4.z, a4.w};
            float bn[4] = {b4.x, b4.y, b4.z, b4.w};
#pragma unroll
            for (int i = 0; i < 4; i++)
#pragma unroll
                for (int j = 0; j < 4; j++) acc[i][j] = fmaf(am[i], bn[j], acc[i][j]);
        }
    }

    if (n0 < A_) {
        // wx: row-major [m][a]
#pragma unroll
        for (int i = 0; i < 4; i++) {
            float4 o = make_float4(acc[i][0], acc[i][1], acc[i][2], acc[i][3]);
            *(float4*)(g_wx + (size_t)(m0 + tm + i) * A_ + n0 + tn) = o;
        }
    } else {
        // ux: transposed store -> g_uxt[b][a][s]
        int b  = m0 / S_;
        int s0 = (m0 % S_) + tm;
        int a0 = (n0 - A_) + tn;
        float* base = g_uxt + (size_t)b * A_ * S_;
#pragma unroll
        for (int j = 0; j < 4; j++) {
            float4 o = make_float4(acc[0][j], acc[1][j], acc[2][j], acc[3][j]);
            *(float4*)(base + (size_t)(a0 + j) * S_ + s0) = o;
        }
    }
}

// ---------------- kernel 2: e = tanh-sum, softmax, attn write, colsum ----------------
#define TI 16
#define TJ 128
// dyn smem: e_buf[TI][1024] + wx_s[TI][128] + ux_s[128][TJ] + v_s[128]  ~ 136.5 KB
__global__ __launch_bounds__(512) void attn_e_kernel(
    const float* __restrict__ v, float* __restrict__ attn_out)
{
    extern __shared__ float sm[];
    float* e_buf = sm;                         // TI*1024
    float* wx_s  = e_buf + TI * S_;            // TI*128
    float* ux_s  = wx_s + TI * A_;             // A_*TJ (a-major)
    float* v_s   = ux_s + A_ * TJ;             // 128

    int tid  = threadIdx.x;
    int warp = tid >> 5;                       // 0..15 -> i row
    int lane = tid & 31;                       // -> 4 j's
    int blk  = blockIdx.x;                     // 128 blocks
    int b    = blk >> 6;
    int i0   = (blk & 63) * TI;

    // load wx rows (TI x 128) -- one float4 per thread
    {
        int r = tid >> 5, c = tid & 31;
        *(float4*)(wx_s + r * A_ + 4 * c) =
            *(const float4*)(g_wx + (size_t)(b * S_ + i0 + r) * A_ + 4 * c);
    }
    if (tid < 32) ((float4*)v_s)[tid] = ((const float4*)v)[tid];

    const float* uxt_b = g_uxt + (size_t)b * A_ * S_;

    for (int jt = 0; jt < S_; jt += TJ) {
        __syncthreads();                       // protect ux_s reuse
        // stage ux tile [a][j] : 128 x 128 floats, coalesced gmem, conflict-free STS
        for (int x = tid; x < A_ * (TJ / 4); x += 512) {
            int a = x >> 5, c = x & 31;
            *(float4*)(ux_s + a * TJ + 4 * c) =
                *(const float4*)(uxt_b + (size_t)a * S_ + jt + 4 * c);
        }
        __syncthreads();

        float acc0 = 0.f, acc1 = 0.f, acc2 = 0.f, acc3 = 0.f;
        const float4* wr = (const float4*)(wx_s + warp * A_);
        const float4* vr = (const float4*)v_s;
        const float*  ub = ux_s + 4 * lane;
#pragma unroll 8
        for (int a4 = 0; a4 < A_ / 4; a4++) {
            float4 w4 = wr[a4];
            float4 v4 = vr[a4];
#define DO(c, k) { \
            float4 uu = *(const float4*)(ub + (4 * a4 + k) * TJ); \
            float wc = w4.c, vc = v4.c; \
            acc0 = fmaf(tanh_fast(wc + uu.x), vc, acc0); \
            acc1 = fmaf(tanh_fast(wc + uu.y), vc, acc1); \
            acc2 = fmaf(tanh_fast(wc + uu.z), vc, acc2); \
            acc3 = fmaf(tanh_fast(wc + uu.w), vc, acc3); }
            DO(x, 0) DO(y, 1) DO(z, 2) DO(w, 3)
#undef DO
        }
        *(float4*)(e_buf + (size_t)warp * S_ + jt + 4 * lane) =
            make_float4(acc0, acc1, acc2, acc3);
    }
    __syncthreads();

    // softmax per row: warp per row (16 warps x 16 rows)
    {
        float* row = e_buf + (size_t)warp * S_;
        float m = -1e30f;
        for (int j = lane; j < S_; j += 32) m = fmaxf(m, row[j]);
#pragma unroll
        for (int o = 16; o; o >>= 1) m = fmaxf(m, __shfl_xor_sync(0xffffffffu, m, o));
        float s = 0.f;
        for (int j = lane; j < S_; j += 32) {
            float p = __expf(row[j] - m);
            row[j] = p;
            s += p;
        }
#pragma unroll
        for (int o = 16; o; o >>= 1) s += __shfl_xor_sync(0xffffffffu, s, o);
        float inv = 1.0f / s;
        float* orow = attn_out + (size_t)(b * S_ + i0 + warp) * S_;
        for (int j = lane; j < S_; j += 32) {
            float p = row[j] * inv;
            row[j] = p;
            orow[j] = p;
        }
    }
    __syncthreads();

    // column sums over this block's TI rows -> global colsum
    for (int j = tid; j < S_; j += 512) {
        float s = 0.f;
#pragma unroll
        for (int r = 0; r < TI; r++) s += e_buf[(size_t)r * S_ + j];
        atomicAdd(&g_colsum[b * S_ + j], s);
    }
}

// ---------------- kernel 3: context[b,h] = sum_j colsum[b,j] * lstm[b,j,h] ----------------
__global__ __launch_bounds__(512) void context_kernel(
    const float* __restrict__ lstm, float* __restrict__ ctx)
{
    int b  = blockIdx.x >> 6;                  // 2 * 64 blocks
    int j0 = (blockIdx.x & 63) * 16;
    int h  = threadIdx.x;                      // 512 threads = H
    __shared__ float cs[16];
    if (threadIdx.x < 16) cs[threadIdx.x] = g_colsum[b * S_ + j0 + threadIdx.x];
    __syncthreads();
    float acc = 0.f;
    const float* lp = lstm + ((size_t)(b * S_ + j0)) * H_ + h;
#pragma unroll
    for (int j = 0; j < 16; j++) acc = fmaf(cs[j], lp[(size_t)j * H_], acc);
    atomicAdd(&ctx[b * H_ + h], acc);
}

// ---------------- launch ----------------
extern "C" void kernel_launch(void* const* d_in, const int* in_sizes, int n_in,
                              void* d_out, int out_size)
{
    const float* lstm = (const float*)d_in[0];
    const float* w    = (const float*)d_in[1];
    const float* u    = (const float*)d_in[2];
    const float* v    = (const float*)d_in[3];
    float* out  = (float*)d_out;
    float* ctx  = out;                // (B,H) = 1024 floats first
    float* attn = out + B_ * H_;      // (B,S,S) = 2M floats after

    zero_kernel<<<8, 256>>>(ctx);
    gemm_wxux<<<dim3(32, 4), 256>>>(lstm, w, u);

    size_t smem = (size_t)(TI * S_ + TI * A_ + A_ * TJ + A_) * sizeof(float); // ~136.5 KB
    cudaFuncSetAttribute(attn_e_kernel, cudaFuncAttributeMaxDynamicSharedMemorySize, (int)smem);
    attn_e_kernel<<<B_ * (S_ / TI), 512, smem>>>(v, attn);

    context_kernel<<<B_ * 64, 512>>>(lstm, ctx);
}